// round 15
// baseline (speedup 1.0000x reference)
#include <cuda_runtime.h>
#include <cuda_fp16.h>
#include <cstdint>

#define NMAX 100000
#define EMAX 2000000
#define HEADS 8
#define F 128
#define NEG_SLOPE 0.2f
#define LOG2E 1.4426950408889634f

// ---------------- static scratch (no allocation) ----------------
// +1 row: sentinel node NMAX (asrc = -1e30 -> weight exactly 0, h row = 0)
__device__ __align__(16) float g_h[(size_t)(NMAX + 1) * F];   // 51.2 MB fp32
__device__ __align__(16) float g_asrc[(NMAX + 1) * HEADS];
__device__ __align__(16) float g_adst[NMAX * HEADS];
__device__ int g_cnt[NMAX];
__device__ int g_start[NMAX];
__device__ int g_cursor[NMAX];
__device__ __align__(16) int g_esrc[EMAX];
__device__ int g_bsum[256];
__device__ int g_idx64;
__device__ int g_bar0, g_bar1;

__device__ __forceinline__ float ex2f(float x) {
    float y; asm("ex2.approx.f32 %0, %1;" : "=f"(y) : "f"(x)); return y;
}

// ---------------- node transform + init ----------------
__global__ void __launch_bounds__(128) node_kernel(
    const float* __restrict__ x, const float* __restrict__ W,
    const float* __restrict__ att_src, const float* __restrict__ att_dst,
    const long long* __restrict__ ei, long long E, int nodes)
{
    const int gid = blockIdx.x * 128 + threadIdx.x;
    if (gid < nodes) g_cnt[gid] = 0;
    if (blockIdx.x == 0) {
        if (threadIdx.x == 0) { g_bar0 = 0; g_bar1 = 0; }
        if (threadIdx.x < 8)  g_asrc[NMAX * HEADS + threadIdx.x] = -1e30f;
        g_h[(size_t)NMAX * F + threadIdx.x] = 0.f;   // zero sentinel row
        if (threadIdx.x < 32) {
            long long stride = E / 32;
            if (stride < 1) stride = 1;
            long long v = ei[stride * threadIdx.x];
            unsigned bad = __ballot_sync(0xffffffffu, v < 0 || v >= NMAX);
            if (threadIdx.x == 0) g_idx64 = (bad == 0u);
        }
    }

    __shared__ float sW[16 * F];
    __shared__ float sx[32][16];
    const int t = threadIdx.x;
    for (int i = t; i < 16 * F; i += 128) sW[i] = W[i];

    const int base = blockIdx.x * 32;
    const int nrem = min(32, nodes - base);
    if (nrem <= 0) return;
    if (t < (nrem * 16) / 4)
        ((float4*)&sx[0][0])[t] = ((const float4*)(x + (size_t)base * 16))[t];
    __syncthreads();

    const int head = t >> 4;
    const int c    = t & 15;
    const float as = att_src[t];
    const float ad = att_dst[t];

    for (int nn = 0; nn < nrem; nn++) {
        const int n = base + nn;
        float hj = 0.f;
        #pragma unroll
        for (int k = 0; k < 16; k++)
            hj = fmaf(sx[nn][k], sW[k * F + t], hj);

        float s1 = hj * as, s2 = hj * ad;
        #pragma unroll
        for (int off = 8; off; off >>= 1) {
            s1 += __shfl_xor_sync(0xffffffffu, s1, off, 16);
            s2 += __shfl_xor_sync(0xffffffffu, s2, off, 16);
        }
        g_h[(size_t)n * F + t] = hj;
        if (c == 0) {
            g_asrc[n * HEADS + head] = s1 * LOG2E;
            g_adst[n * HEADS + head] = s2 * LOG2E;
        }
    }
}

// ---------------- histogram ----------------
__global__ void hist_kernel(const long long* __restrict__ ei64,
                            const int* __restrict__ ei32, long long E) {
    const long long base = (long long)blockIdx.x * 1024 + threadIdx.x;
    const int use64 = g_idx64;
    #pragma unroll
    for (int i = 0; i < 4; i++) {
        long long e = base + i * 256;
        if (e < E) {
            int dst = use64 ? (int)ei64[E + e] : ei32[E + e];
            atomicAdd(&g_cnt[dst], 1);
        }
    }
}

// ---------------- fused scan (padded) + padding-fill + scatter ----------------
__device__ __forceinline__ void grid_bar(int* ctr, int expected) {
    __syncthreads();
    __threadfence();
    if (threadIdx.x == 0) {
        atomicAdd(ctr, 1);
        while (*(volatile int*)ctr < expected) { }
    }
    __syncthreads();
}

__global__ void __launch_bounds__(512) csr_kernel(
    const long long* __restrict__ ei64, const int* __restrict__ ei32,
    long long E, int nodes)
{
    __shared__ int sh[512];
    __shared__ int sbs[256];
    const int t = threadIdx.x, b = blockIdx.x;
    const int i = b * 512 + t;

    const int cnt = (i < nodes) ? g_cnt[i] : 0;
    const int c = (cnt + 3) & ~3;
    sh[t] = c; __syncthreads();
    for (int off = 1; off < 512; off <<= 1) {
        int v = (t >= off) ? sh[t - off] : 0;
        __syncthreads();
        sh[t] += v;
        __syncthreads();
    }
    if (t == 511) g_bsum[b] = sh[511];
    const int excl = sh[t] - c;

    grid_bar(&g_bar0, 256);

    if (t < 256) sbs[t] = g_bsum[t];
    __syncthreads();
    for (int off = 1; off < 256; off <<= 1) {
        int v = (t >= off && t < 256) ? sbs[t - off] : 0;
        __syncthreads();
        if (t < 256) sbs[t] += v;
        __syncthreads();
    }
    const int blockbase = (b > 0) ? sbs[b - 1] : 0;
    if (i < nodes) {
        const int s = blockbase + excl;
        g_start[i]  = s;
        g_cursor[i] = s;
        for (int k = cnt; k < c; k++) g_esrc[s + k] = NMAX;
    }

    grid_bar(&g_bar1, 256);

    const int use64 = g_idx64;
    const long long NT = 256LL * 512;
    for (long long e = (long long)b * 512 + t; e < E; e += NT) {
        int src, dst;
        if (use64) { src = (int)ei64[e]; dst = (int)ei64[E + e]; }
        else       { src = ei32[e];      dst = ei32[E + e]; }
        int pos = atomicAdd(&g_cursor[dst], 1);
        g_esrc[pos] = src;
    }
}

// ---------------- gather + finalize (1 warp/node, pipelined idx) ----------
__global__ void __launch_bounds__(256, 6) gather_kernel(
    const float* __restrict__ bias, const float* __restrict__ fc_w,
    const float* __restrict__ fc_b, float* __restrict__ out, int nodes)
{
    __shared__ __align__(16) float sb[F];
    __shared__ __align__(16) float sw[5][F];
    __shared__ float sfb[5];
    const int t = threadIdx.x;
    for (int i = t; i < F; i += 256) sb[i] = bias[i];
    for (int i = t; i < 5 * F; i += 256) { int j = i / 5, k = i % 5; sw[k][j] = fc_w[i]; }
    if (t < 5) sfb[t] = fc_b[t];
    __syncthreads();

    const int n = blockIdx.x * 8 + (t >> 5);
    if (n >= nodes) return;
    const int lane = t & 31;
    const int h = lane >> 2;
    const int j0 = lane * 4;

    const float adw = g_adst[n * HEADS + h];
    const float* __restrict__ asrch = g_asrc + h;            // [idx*8]
    const ulonglong2* __restrict__ hb =
        (const ulonglong2*)(g_h + j0);                        // [idx*32]

    unsigned long long accxy = 0ull, acczw = 0ull;
    float dsum = 0.f;

    // self loop
    {
        float a = asrch[(size_t)n * 8] + adw;
        a = fmaxf(a, NEG_SLOPE * a);
        float w = ex2f(a);
        ulonglong2 v = hb[(size_t)n * 32];
        unsigned long long w2;
        asm("mov.b64 %0, {%1,%1};" : "=l"(w2) : "f"(w));
        asm("fma.rn.f32x2 %0, %1, %2, %0;" : "+l"(accxy) : "l"(w2), "l"(v.x));
        asm("fma.rn.f32x2 %0, %1, %2, %0;" : "+l"(acczw) : "l"(w2), "l"(v.y));
        dsum = w;
    }

    const int s0 = g_start[n];
    const int groups = (g_cnt[n] + 3) >> 2;

    if (groups > 0) {
        int4 iv = *(const int4*)&g_esrc[s0];          // first group's indices
        for (int g = 0; g < groups; g++) {
            // prefetch next group's indices (sentinel-safe dummy on last iter)
            const int nxt = (g + 1 < groups) ? (g + 1) : 0;
            int4 ivn = *(const int4*)&g_esrc[s0 + nxt * 4];

            float a0 = asrch[(size_t)iv.x * 8] + adw;
            float a1 = asrch[(size_t)iv.y * 8] + adw;
            float a2 = asrch[(size_t)iv.z * 8] + adw;
            float a3 = asrch[(size_t)iv.w * 8] + adw;
            ulonglong2 v0 = hb[(size_t)iv.x * 32];
            ulonglong2 v1 = hb[(size_t)iv.y * 32];
            ulonglong2 v2 = hb[(size_t)iv.z * 32];
            ulonglong2 v3 = hb[(size_t)iv.w * 32];
            a0 = fmaxf(a0, NEG_SLOPE * a0); float w0 = ex2f(a0);
            a1 = fmaxf(a1, NEG_SLOPE * a1); float w1 = ex2f(a1);
            a2 = fmaxf(a2, NEG_SLOPE * a2); float w2 = ex2f(a2);
            a3 = fmaxf(a3, NEG_SLOPE * a3); float w3 = ex2f(a3);
            dsum += (w0 + w1) + (w2 + w3);
            unsigned long long p0, p1, p2, p3;
            asm("mov.b64 %0, {%1,%1};" : "=l"(p0) : "f"(w0));
            asm("mov.b64 %0, {%1,%1};" : "=l"(p1) : "f"(w1));
            asm("mov.b64 %0, {%1,%1};" : "=l"(p2) : "f"(w2));
            asm("mov.b64 %0, {%1,%1};" : "=l"(p3) : "f"(w3));
            asm("fma.rn.f32x2 %0, %1, %2, %0;" : "+l"(accxy) : "l"(p0), "l"(v0.x));
            asm("fma.rn.f32x2 %0, %1, %2, %0;" : "+l"(acczw) : "l"(p0), "l"(v0.y));
            asm("fma.rn.f32x2 %0, %1, %2, %0;" : "+l"(accxy) : "l"(p1), "l"(v1.x));
            asm("fma.rn.f32x2 %0, %1, %2, %0;" : "+l"(acczw) : "l"(p1), "l"(v1.y));
            asm("fma.rn.f32x2 %0, %1, %2, %0;" : "+l"(accxy) : "l"(p2), "l"(v2.x));
            asm("fma.rn.f32x2 %0, %1, %2, %0;" : "+l"(acczw) : "l"(p2), "l"(v2.y));
            asm("fma.rn.f32x2 %0, %1, %2, %0;" : "+l"(accxy) : "l"(p3), "l"(v3.x));
            asm("fma.rn.f32x2 %0, %1, %2, %0;" : "+l"(acczw) : "l"(p3), "l"(v3.y));

            iv = ivn;
        }
    }

    float ax, ay, az, aw;
    asm("mov.b64 {%0,%1}, %2;" : "=f"(ax), "=f"(ay) : "l"(accxy));
    asm("mov.b64 {%0,%1}, %2;" : "=f"(az), "=f"(aw) : "l"(acczw));

    const float inv = 1.f / (dsum + 1e-16f);
    const float4 bv = *(const float4*)&sb[j0];
    float o0 = fmaxf(fmaf(ax, inv, bv.x), 0.f);
    float o1 = fmaxf(fmaf(ay, inv, bv.y), 0.f);
    float o2 = fmaxf(fmaf(az, inv, bv.z), 0.f);
    float o3 = fmaxf(fmaf(aw, inv, bv.w), 0.f);

    float p[5];
    #pragma unroll
    for (int k = 0; k < 5; k++) {
        const float4 wv = *(const float4*)&sw[k][j0];
        p[k] = o0 * wv.x + o1 * wv.y + o2 * wv.z + o3 * wv.w;
    }
    #pragma unroll
    for (int off = 16; off; off >>= 1) {
        #pragma unroll
        for (int k = 0; k < 5; k++)
            p[k] += __shfl_xor_sync(0xffffffffu, p[k], off);
    }
    if (lane == 0) {
        #pragma unroll
        for (int k = 0; k < 5; k++) p[k] += sfb[k];
        float m = p[0];
        #pragma unroll
        for (int k = 1; k < 5; k++) m = fmaxf(m, p[k]);
        float s = 0.f;
        #pragma unroll
        for (int k = 0; k < 5; k++) s += __expf(p[k] - m);
        const float lse = m + logf(s);
        #pragma unroll
        for (int k = 0; k < 5; k++)
            out[(size_t)n * 5 + k] = p[k] - lse;
    }
}

// ---------------- launch ----------------
extern "C" void kernel_launch(void* const* d_in, const int* in_sizes, int n_in,
                              void* d_out, int out_size)
{
    const float* x       = (const float*)d_in[0];
    const void*  ei      = d_in[1];
    const float* W       = (const float*)d_in[2];
    const float* att_src = (const float*)d_in[3];
    const float* att_dst = (const float*)d_in[4];
    const float* bias    = (const float*)d_in[5];
    const float* fc_w    = (const float*)d_in[6];
    const float* fc_b    = (const float*)d_in[7];
    float* out = (float*)d_out;

    const int nodes = in_sizes[0] / 16;
    const long long E = (long long)in_sizes[1] / 2;

    node_kernel<<<(nodes + 31) / 32, 128>>>(x, W, att_src, att_dst,
                                            (const long long*)ei, E, nodes);
    hist_kernel<<<(int)((E + 1023) / 1024), 256>>>((const long long*)ei, (const int*)ei, E);
    csr_kernel<<<256, 512>>>((const long long*)ei, (const int*)ei, E, nodes);
    gather_kernel<<<(nodes + 7) / 8, 256>>>(bias, fc_w, fc_b, out, nodes);
}

// round 16
// speedup vs baseline: 1.4925x; 1.4925x over previous
#include <cuda_runtime.h>
#include <cstdint>

#define NMAX 100000
#define EMAX 2000000
#define HEADS 8
#define F 128
#define NEG_SLOPE 0.2f
#define LOG2E 1.4426950408889634f

// ---------------- static scratch (no allocation) ----------------
// +1 row: sentinel node NMAX (asrc = -1e30 -> weight exactly 0, h row = 0)
__device__ __align__(16) float g_h[(size_t)(NMAX + 1) * F];   // 51.2 MB fp32
__device__ __align__(16) float g_asrc[(NMAX + 1) * HEADS];
__device__ __align__(16) float g_adst[NMAX * HEADS];
__device__ int g_cnt[NMAX];          // zero-initialized at load; csr re-zeroes each run
__device__ int g_start[NMAX + 1];
__device__ int g_cursor[NMAX];
__device__ __align__(16) int g_esrc[EMAX];
__device__ int g_bsum[256];
__device__ int g_idx64;
__device__ int g_bar0, g_bar1;

__device__ __forceinline__ float ex2f(float x) {
    float y; asm("ex2.approx.f32 %0, %1;" : "=f"(y) : "f"(x)); return y;
}

// ---------------- node transform + fused histogram ----------------
__global__ void __launch_bounds__(128) node_kernel(
    const float* __restrict__ x, const float* __restrict__ W,
    const float* __restrict__ att_src, const float* __restrict__ att_dst,
    const long long* __restrict__ ei64, const int* __restrict__ ei32,
    long long E, int nodes, int nblocks)
{
    __shared__ float sW[16 * F];
    __shared__ float sx[32][16];
    __shared__ int s_use64;
    const int t = threadIdx.x;

    // per-block dtype sniff (no cross-block dependency)
    if (t < 32) {
        long long stride = E / 32;
        if (stride < 1) stride = 1;
        long long v = ei64[stride * t];
        unsigned bad = __ballot_sync(0xffffffffu, v < 0 || v >= NMAX);
        if (t == 0) {
            s_use64 = (bad == 0u);
            if (blockIdx.x == 0) g_idx64 = s_use64;   // for later kernels
        }
    }
    if (blockIdx.x == 0) {
        if (t == 0) { g_bar0 = 0; g_bar1 = 0; }
        if (t < 8)  g_asrc[NMAX * HEADS + t] = -1e30f;
        g_h[(size_t)NMAX * F + t] = 0.f;             // zero sentinel row
    }

    for (int i = t; i < 16 * F; i += 128) sW[i] = W[i];

    const int base = blockIdx.x * 32;
    const int nrem = min(32, nodes - base);
    if (nrem > 0) {
        if (t < (nrem * 16) / 4)
            ((float4*)&sx[0][0])[t] = ((const float4*)(x + (size_t)base * 16))[t];
    }
    __syncthreads();

    if (nrem > 0) {
        const int head = t >> 4;
        const int c    = t & 15;
        const float as = att_src[t];
        const float ad = att_dst[t];

        for (int nn = 0; nn < nrem; nn++) {
            const int n = base + nn;
            float hj = 0.f;
            #pragma unroll
            for (int k = 0; k < 16; k++)
                hj = fmaf(sx[nn][k], sW[k * F + t], hj);

            float s1 = hj * as, s2 = hj * ad;
            #pragma unroll
            for (int off = 8; off; off >>= 1) {
                s1 += __shfl_xor_sync(0xffffffffu, s1, off, 16);
                s2 += __shfl_xor_sync(0xffffffffu, s2, off, 16);
            }
            g_h[(size_t)n * F + t] = hj;
            if (c == 0) {
                g_asrc[n * HEADS + head] = s1 * LOG2E;
                g_adst[n * HEADS + head] = s2 * LOG2E;
            }
        }
    }

    // ---- fused histogram: this block's contiguous edge chunk ----
    const int use64 = s_use64;
    const long long chunk = (E + nblocks - 1) / nblocks;
    const long long e0 = (long long)blockIdx.x * chunk;
    const long long e1 = min(e0 + chunk, E);
    for (long long e = e0 + t; e < e1; e += 128) {
        int dst = use64 ? (int)ei64[E + e] : ei32[E + e];
        atomicAdd(&g_cnt[dst], 1);
    }
}

// ---------------- fused scan (padded) + cnt re-zero + padding-fill + scatter ------
__device__ __forceinline__ void grid_bar(int* ctr, int expected) {
    __syncthreads();
    __threadfence();
    if (threadIdx.x == 0) {
        atomicAdd(ctr, 1);
        while (*(volatile int*)ctr < expected) { }
    }
    __syncthreads();
}

__global__ void __launch_bounds__(512) csr_kernel(
    const long long* __restrict__ ei64, const int* __restrict__ ei32,
    long long E, int nodes)
{
    __shared__ int sh[512];
    __shared__ int sbs[256];
    const int t = threadIdx.x, b = blockIdx.x;
    const int i = b * 512 + t;

    const int cnt = (i < nodes) ? g_cnt[i] : 0;
    if (i < nodes) g_cnt[i] = 0;           // clean for next graph replay
    const int c = (cnt + 3) & ~3;          // padded (4-aligned) count
    sh[t] = c; __syncthreads();
    for (int off = 1; off < 512; off <<= 1) {
        int v = (t >= off) ? sh[t - off] : 0;
        __syncthreads();
        sh[t] += v;
        __syncthreads();
    }
    if (t == 511) g_bsum[b] = sh[511];
    const int excl = sh[t] - c;

    grid_bar(&g_bar0, 256);

    if (t < 256) sbs[t] = g_bsum[t];
    __syncthreads();
    for (int off = 1; off < 256; off <<= 1) {
        int v = (t >= off && t < 256) ? sbs[t - off] : 0;
        __syncthreads();
        if (t < 256) sbs[t] += v;
        __syncthreads();
    }
    const int blockbase = (b > 0) ? sbs[b - 1] : 0;
    if (i < nodes) {
        const int s = blockbase + excl;
        g_start[i]  = s;
        g_cursor[i] = s;
        for (int k = cnt; k < c; k++) g_esrc[s + k] = NMAX;   // sentinel padding
    } else if (i == nodes) {
        g_start[i] = blockbase + excl;                         // total (padded)
    }

    grid_bar(&g_bar1, 256);

    const int use64 = g_idx64;
    const long long NT = 256LL * 512;
    for (long long e = (long long)b * 512 + t; e < E; e += NT) {
        int src, dst;
        if (use64) { src = (int)ei64[e]; dst = (int)ei64[E + e]; }
        else       { src = ei32[e];      dst = ei32[E + e]; }
        int pos = atomicAdd(&g_cursor[dst], 1);
        g_esrc[pos] = src;
    }
}

// ---------------- gather + finalize (1 warp/node, f32x2 packed accum) ----------
__global__ void __launch_bounds__(256) gather_kernel(
    const float* __restrict__ bias, const float* __restrict__ fc_w,
    const float* __restrict__ fc_b, float* __restrict__ out, int nodes)
{
    __shared__ __align__(16) float sb[F];
    __shared__ __align__(16) float sw[5][F];
    __shared__ float sfb[5];
    const int t = threadIdx.x;
    for (int i = t; i < F; i += 256) sb[i] = bias[i];
    for (int i = t; i < 5 * F; i += 256) { int j = i / 5, k = i % 5; sw[k][j] = fc_w[i]; }
    if (t < 5) sfb[t] = fc_b[t];
    __syncthreads();

    const int n = blockIdx.x * 8 + (t >> 5);
    if (n >= nodes) return;
    const int lane = t & 31;
    const int h = lane >> 2;
    const int j0 = lane * 4;

    const float adw = g_adst[n * HEADS + h];
    const float* __restrict__ asrch = g_asrc + h;            // [idx*8]
    const ulonglong2* __restrict__ hb =
        (const ulonglong2*)(g_h + j0);                        // [idx*32] (512B rows)

    unsigned long long accxy = 0ull, acczw = 0ull;            // packed f32x2
    float dsum = 0.f;

    // self loop
    {
        float a = asrch[(size_t)n * 8] + adw;
        a = fmaxf(a, NEG_SLOPE * a);
        float w = ex2f(a);
        ulonglong2 v = hb[(size_t)n * 32];
        unsigned long long w2;
        asm("mov.b64 %0, {%1,%1};" : "=l"(w2) : "f"(w));
        asm("fma.rn.f32x2 %0, %1, %2, %0;" : "+l"(accxy) : "l"(w2), "l"(v.x));
        asm("fma.rn.f32x2 %0, %1, %2, %0;" : "+l"(acczw) : "l"(w2), "l"(v.y));
        dsum = w;
    }

    const int s0 = g_start[n];
    const int groups = (g_start[n + 1] - s0) >> 2;

    for (int g = 0; g < groups; g++) {
        const int4 iv = *(const int4*)&g_esrc[s0 + g * 4];
        float a0 = asrch[(size_t)iv.x * 8] + adw;
        float a1 = asrch[(size_t)iv.y * 8] + adw;
        float a2 = asrch[(size_t)iv.z * 8] + adw;
        float a3 = asrch[(size_t)iv.w * 8] + adw;
        ulonglong2 v0 = hb[(size_t)iv.x * 32];
        ulonglong2 v1 = hb[(size_t)iv.y * 32];
        ulonglong2 v2 = hb[(size_t)iv.z * 32];
        ulonglong2 v3 = hb[(size_t)iv.w * 32];
        a0 = fmaxf(a0, NEG_SLOPE * a0); float w0 = ex2f(a0);
        a1 = fmaxf(a1, NEG_SLOPE * a1); float w1 = ex2f(a1);
        a2 = fmaxf(a2, NEG_SLOPE * a2); float w2 = ex2f(a2);
        a3 = fmaxf(a3, NEG_SLOPE * a3); float w3 = ex2f(a3);
        dsum += (w0 + w1) + (w2 + w3);
        unsigned long long p0, p1, p2, p3;
        asm("mov.b64 %0, {%1,%1};" : "=l"(p0) : "f"(w0));
        asm("mov.b64 %0, {%1,%1};" : "=l"(p1) : "f"(w1));
        asm("mov.b64 %0, {%1,%1};" : "=l"(p2) : "f"(w2));
        asm("mov.b64 %0, {%1,%1};" : "=l"(p3) : "f"(w3));
        asm("fma.rn.f32x2 %0, %1, %2, %0;" : "+l"(accxy) : "l"(p0), "l"(v0.x));
        asm("fma.rn.f32x2 %0, %1, %2, %0;" : "+l"(acczw) : "l"(p0), "l"(v0.y));
        asm("fma.rn.f32x2 %0, %1, %2, %0;" : "+l"(accxy) : "l"(p1), "l"(v1.x));
        asm("fma.rn.f32x2 %0, %1, %2, %0;" : "+l"(acczw) : "l"(p1), "l"(v1.y));
        asm("fma.rn.f32x2 %0, %1, %2, %0;" : "+l"(accxy) : "l"(p2), "l"(v2.x));
        asm("fma.rn.f32x2 %0, %1, %2, %0;" : "+l"(acczw) : "l"(p2), "l"(v2.y));
        asm("fma.rn.f32x2 %0, %1, %2, %0;" : "+l"(accxy) : "l"(p3), "l"(v3.x));
        asm("fma.rn.f32x2 %0, %1, %2, %0;" : "+l"(acczw) : "l"(p3), "l"(v3.y));
    }

    float ax, ay, az, aw;
    asm("mov.b64 {%0,%1}, %2;" : "=f"(ax), "=f"(ay) : "l"(accxy));
    asm("mov.b64 {%0,%1}, %2;" : "=f"(az), "=f"(aw) : "l"(acczw));

    const float inv = 1.f / (dsum + 1e-16f);
    const float4 bv = *(const float4*)&sb[j0];
    float o0 = fmaxf(fmaf(ax, inv, bv.x), 0.f);
    float o1 = fmaxf(fmaf(ay, inv, bv.y), 0.f);
    float o2 = fmaxf(fmaf(az, inv, bv.z), 0.f);
    float o3 = fmaxf(fmaf(aw, inv, bv.w), 0.f);

    float p[5];
    #pragma unroll
    for (int k = 0; k < 5; k++) {
        const float4 wv = *(const float4*)&sw[k][j0];
        p[k] = o0 * wv.x + o1 * wv.y + o2 * wv.z + o3 * wv.w;
    }
    #pragma unroll
    for (int off = 16; off; off >>= 1) {
        #pragma unroll
        for (int k = 0; k < 5; k++)
            p[k] += __shfl_xor_sync(0xffffffffu, p[k], off);
    }
    if (lane == 0) {
        #pragma unroll
        for (int k = 0; k < 5; k++) p[k] += sfb[k];
        float m = p[0];
        #pragma unroll
        for (int k = 1; k < 5; k++) m = fmaxf(m, p[k]);
        float s = 0.f;
        #pragma unroll
        for (int k = 0; k < 5; k++) s += __expf(p[k] - m);
        const float lse = m + logf(s);
        #pragma unroll
        for (int k = 0; k < 5; k++)
            out[(size_t)n * 5 + k] = p[k] - lse;
    }
}

// ---------------- launch ----------------
extern "C" void kernel_launch(void* const* d_in, const int* in_sizes, int n_in,
                              void* d_out, int out_size)
{
    const float* x       = (const float*)d_in[0];
    const void*  ei      = d_in[1];
    const float* W       = (const float*)d_in[2];
    const float* att_src = (const float*)d_in[3];
    const float* att_dst = (const float*)d_in[4];
    const float* bias    = (const float*)d_in[5];
    const float* fc_w    = (const float*)d_in[6];
    const float* fc_b    = (const float*)d_in[7];
    float* out = (float*)d_out;

    const int nodes = in_sizes[0] / 16;
    const long long E = (long long)in_sizes[1] / 2;
    const int nblocks = (nodes + 31) / 32;

    node_kernel<<<nblocks, 128>>>(x, W, att_src, att_dst,
                                  (const long long*)ei, (const int*)ei,
                                  E, nodes, nblocks);
    csr_kernel<<<256, 512>>>((const long long*)ei, (const int*)ei, E, nodes);
    gather_kernel<<<(nodes + 7) / 8, 256>>>(bias, fc_w, fc_b, out, nodes);
}